// round 2
// baseline (speedup 1.0000x reference)
#include <cuda_runtime.h>
#include <cstdint>

#define F_DIM 512
#define H_DIM 256
#define NLOC_ 12
#define MAXB 16384

__device__ __align__(16) float g_Bt1[768 * 512];
__device__ __align__(16) float g_Bt3[512 * 768];
__device__ __align__(16) float g_ct[512];
__device__ __align__(16) float g_bf3[512];
__device__ float g_S[1];
__device__ __align__(16) float g_t[(size_t)MAXB * 512];
__device__ __align__(16) float g_X[(size_t)MAXB * 768];
__device__ __align__(16) float g_lf[(size_t)MAXB * 512];

__device__ __forceinline__ float f2tf32(float x) {
    uint32_t u;
    asm("cvt.rna.tf32.f32 %0, %1;" : "=r"(u) : "f"(x));
    return __uint_as_float(u);
}
__device__ __forceinline__ void cp16(float* dst, const float* src) {
    uint32_t sa = (uint32_t)__cvta_generic_to_shared(dst);
    asm volatile("cp.async.cg.shared.global [%0], [%1], 16;" ::"r"(sa), "l"(src));
}
__device__ __forceinline__ void mma8(float c[4], const uint32_t a[4], const uint32_t b[2]) {
    asm volatile(
        "mma.sync.aligned.m16n8k8.row.col.f32.tf32.tf32.f32 "
        "{%0,%1,%2,%3},{%4,%5,%6,%7},{%8,%9},{%0,%1,%2,%3};"
        : "+f"(c[0]), "+f"(c[1]), "+f"(c[2]), "+f"(c[3])
        : "r"(a[0]), "r"(a[1]), "r"(a[2]), "r"(a[3]), "r"(b[0]), "r"(b[1]));
}

// Bt1[n][g] = sum_h Wk[n,h]*Wq[g,h]
__global__ void prep_bt1_mm(const float* __restrict__ Wk, const float* __restrict__ Wq) {
    __shared__ float sK[16][17], sQ[16][17];
    int tx = threadIdx.x, ty = threadIdx.y;
    int n0 = blockIdx.y * 16, g0 = blockIdx.x * 16;
    float acc = 0.f;
    for (int h0 = 0; h0 < 256; h0 += 16) {
        sK[ty][tx] = Wk[(n0 + ty) * 256 + h0 + tx];
        sQ[ty][tx] = Wq[(g0 + ty) * 256 + h0 + tx];
        __syncthreads();
#pragma unroll
        for (int hh = 0; hh < 16; hh++) acc += sK[ty][hh] * sQ[tx][hh];
        __syncthreads();
    }
    g_Bt1[(n0 + ty) * 512 + g0 + tx] = f2tf32(acc);
}
// Bt1[512+h][g] = Wv[g][h]
__global__ void prep_bt1_cp(const float* __restrict__ Wv) {
    int i = blockIdx.x * 256 + threadIdx.x;
    int h = i >> 9, g = i & 511;
    g_Bt1[(512 + h) * 512 + g] = f2tf32(Wv[g * 256 + h]);
}
// Bt3[n][k] = sum_h Wf[h,n]*Wv[k,h]  (k<512)
__global__ void prep_bt3_mm(const float* __restrict__ Wf, const float* __restrict__ Wv) {
    __shared__ float sF[16][17], sV[16][17];
    int tx = threadIdx.x, ty = threadIdx.y;  // tx->k, ty->n
    int k0 = blockIdx.x * 16, n0 = blockIdx.y * 16;
    float acc = 0.f;
    for (int h0 = 0; h0 < 256; h0 += 16) {
        sF[ty][tx] = Wf[(h0 + ty) * 512 + n0 + tx];  // sF[h][n]
        sV[ty][tx] = Wv[(k0 + ty) * 256 + h0 + tx];  // sV[k][h]
        __syncthreads();
#pragma unroll
        for (int hh = 0; hh < 16; hh++) acc += sF[hh][ty] * sV[tx][hh];
        __syncthreads();
    }
    g_Bt3[(n0 + ty) * 768 + k0 + tx] = f2tf32(acc);
}
// Bt3[n][512+j] = Wf[256+j][n]
__global__ void prep_bt3_cp(const float* __restrict__ Wf) {
    int i = blockIdx.x * 256 + threadIdx.x;
    int n = i >> 8, j = i & 255;
    g_Bt3[n * 768 + 512 + j] = f2tf32(Wf[(256 + j) * 512 + n]);
}
__global__ void prep_vec(const float* __restrict__ bq, const float* __restrict__ Wk,
                         const float* __restrict__ bv, const float* __restrict__ Wf,
                         const float* __restrict__ bf, const float* __restrict__ w_dr) {
    int tid = blockIdx.x * blockDim.x + threadIdx.x;
    if (tid < 512) {
        float a = 0.f;
        for (int h = 0; h < 256; h++) a += bq[h] * Wk[tid * 256 + h];
        g_ct[tid] = a;
    } else if (tid < 1024) {
        int n = tid - 512;
        float a = bf[n];
        for (int h = 0; h < 256; h++) a += bv[h] * Wf[h * 512 + n];
        g_bf3[n] = a;
    }
    if (tid == 0) {
        float s = 0.f;
        for (int k = 0; k < NLOC_; k++) s += w_dr[k];
        g_S[0] = s;
    }
}

// 128x128x16 tf32 mma GEMM, double-buffered cp.async.
// MODE 1: A=global [B,512], Bt=g_Bt1[768][512]; n<512 -> g_t=acc+ct; n>=512 -> g_X[:,n]=tf32((acc+bv)*S+b_dr)
// MODE 3: A=g_X [B,768], Bt=g_Bt3[512][768]; out = relu(acc+bf3) + g_lf + global
template <int MODE>
__global__ __launch_bounds__(256) void gemm_tf32(const float* __restrict__ Aext,
                                                 const float* __restrict__ bv,
                                                 const float* __restrict__ b_dr,
                                                 const float* __restrict__ globalf,
                                                 float* __restrict__ out) {
    constexpr int BM = 128, BN = 128, BK = 16, LD = 20;
    constexpr int KTOT = (MODE == 1) ? 512 : 768;
    constexpr int LDA = KTOT, LDB = KTOT;
    constexpr int KT = KTOT / BK;
    const float* A = (MODE == 1) ? Aext : g_X;
    const float* Bt = (MODE == 1) ? g_Bt1 : g_Bt3;

    __shared__ __align__(16) float As[2][BM * LD];
    __shared__ __align__(16) float Bs[2][BN * LD];

    int tid = threadIdx.x;
    int warp = tid >> 5, lane = tid & 31;
    int wm = warp >> 2, wn = warp & 3;  // 2x4 warps -> 64x32 each
    int qr = lane >> 2, qc = lane & 3;
    int m0 = blockIdx.y * BM, n0 = blockIdx.x * BN;

    float acc[4][4][4];
#pragma unroll
    for (int i = 0; i < 4; i++)
#pragma unroll
        for (int j = 0; j < 4; j++)
#pragma unroll
            for (int q = 0; q < 4; q++) acc[i][j][q] = 0.f;

    int lr = tid >> 1;
    int lc = (tid & 1) * 8;
    const float* Ag = A + (size_t)(m0 + lr) * LDA + lc;
    const float* Bg = Bt + (size_t)(n0 + lr) * LDB + lc;

    {
        float* sa = &As[0][lr * LD + lc];
        float* sb = &Bs[0][lr * LD + lc];
        cp16(sa, Ag); cp16(sa + 4, Ag + 4);
        cp16(sb, Bg); cp16(sb + 4, Bg + 4);
        asm volatile("cp.async.commit_group;");
    }

    for (int kt = 0; kt < KT; kt++) {
        int cur = kt & 1;
        if (kt + 1 < KT) {
            const float* ap = Ag + (kt + 1) * BK;
            const float* bp = Bg + (kt + 1) * BK;
            float* sa = &As[cur ^ 1][lr * LD + lc];
            float* sb = &Bs[cur ^ 1][lr * LD + lc];
            cp16(sa, ap); cp16(sa + 4, ap + 4);
            cp16(sb, bp); cp16(sb + 4, bp + 4);
            asm volatile("cp.async.commit_group;");
            asm volatile("cp.async.wait_group 1;");
        } else {
            asm volatile("cp.async.wait_group 0;");
        }
        __syncthreads();

#pragma unroll
        for (int kk = 0; kk < 2; kk++) {
            uint32_t af[4][4];
#pragma unroll
            for (int i = 0; i < 4; i++) {
                int r0 = wm * 64 + i * 16 + qr;
                const float* s = &As[cur][0];
                af[i][0] = __float_as_uint(s[r0 * LD + kk * 8 + qc]);
                af[i][1] = __float_as_uint(s[(r0 + 8) * LD + kk * 8 + qc]);
                af[i][2] = __float_as_uint(s[r0 * LD + kk * 8 + qc + 4]);
                af[i][3] = __float_as_uint(s[(r0 + 8) * LD + kk * 8 + qc + 4]);
            }
            uint32_t bfr[4][2];
#pragma unroll
            for (int j = 0; j < 4; j++) {
                int nn = wn * 32 + j * 8 + qr;
                const float* s = &Bs[cur][0];
                bfr[j][0] = __float_as_uint(s[nn * LD + kk * 8 + qc]);
                bfr[j][1] = __float_as_uint(s[nn * LD + kk * 8 + qc + 4]);
            }
#pragma unroll
            for (int i = 0; i < 4; i++)
#pragma unroll
                for (int j = 0; j < 4; j++) mma8(acc[i][j], af[i], bfr[j]);
        }
        __syncthreads();
    }

    float Sv = 0.f, bdv = 0.f;
    if (MODE == 1) { Sv = g_S[0]; bdv = b_dr[0]; }
#pragma unroll
    for (int i = 0; i < 4; i++) {
        int row = m0 + wm * 64 + i * 16 + qr;
#pragma unroll
        for (int j = 0; j < 4; j++) {
            int col = n0 + wn * 32 + j * 8 + qc * 2;
#pragma unroll
            for (int q = 0; q < 4; q++) {
                int rr = row + ((q >= 2) ? 8 : 0);
                int cc = col + (q & 1);
                float v = acc[i][j][q];
                if (MODE == 1) {
                    if (cc < 512) {
                        g_t[(size_t)rr * 512 + cc] = v + g_ct[cc];
                    } else {
                        g_X[(size_t)rr * 768 + cc] = f2tf32((v + bv[cc - 512]) * Sv + bdv);
                    }
                } else {
                    float z = fmaxf(v + g_bf3[cc], 0.f);
                    out[(size_t)rr * 512 + cc] =
                        z + g_lf[(size_t)rr * 512 + cc] + globalf[(size_t)rr * 512 + cc];
                }
            }
        }
    }
}

// Per-row: scores s2 = (local . t)/16, softmax over 12, pooled -> g_X[:,0:512] (tf32),
// lf_mean -> g_lf. Reads local exactly once.
__global__ __launch_bounds__(256) void attn_pool(const float* __restrict__ local,
                                                 const float* __restrict__ w_dr,
                                                 const float* __restrict__ b_dr) {
    __shared__ float ls[NLOC_ * 512];
    __shared__ float sred[NLOC_][8];
    __shared__ float a2s[NLOC_];
    __shared__ float wds[NLOC_];
    int b = blockIdx.x;
    int tid = threadIdx.x;
    const float* lb = local + (size_t)b * NLOC_ * 512;
    for (int i = tid; i < NLOC_ * 512; i += 256) ls[i] = lb[i];
    if (tid < NLOC_) wds[tid] = w_dr[tid];
    float tt0 = g_t[(size_t)b * 512 + tid];
    float tt1 = g_t[(size_t)b * 512 + tid + 256];
    __syncthreads();

    float p[NLOC_];
#pragma unroll
    for (int k = 0; k < NLOC_; k++)
        p[k] = ls[k * 512 + tid] * tt0 + ls[k * 512 + tid + 256] * tt1;
#pragma unroll
    for (int k = 0; k < NLOC_; k++)
#pragma unroll
        for (int off = 16; off; off >>= 1) p[k] += __shfl_xor_sync(0xffffffffu, p[k], off);
    if ((tid & 31) == 0) {
        int w = tid >> 5;
#pragma unroll
        for (int k = 0; k < NLOC_; k++) sred[k][w] = p[k];
    }
    __syncthreads();
    if (tid == 0) {
        float s[NLOC_], m = -1e30f;
#pragma unroll
        for (int k = 0; k < NLOC_; k++) {
            float v = 0.f;
#pragma unroll
            for (int w = 0; w < 8; w++) v += sred[k][w];
            v *= 0.0625f;  // 1/sqrt(256)
            s[k] = v;
            m = fmaxf(m, v);
        }
        float den = 0.f;
#pragma unroll
        for (int k = 0; k < NLOC_; k++) { s[k] = __expf(s[k] - m); den += s[k]; }
        float inv = 1.f / den;
#pragma unroll
        for (int k = 0; k < NLOC_; k++) a2s[k] = s[k] * inv;
    }
    __syncthreads();
    float bd = b_dr[0];
#pragma unroll
    for (int q = 0; q < 2; q++) {
        int f = tid + q * 256;
        float pool = 0.f, lfv = 0.f;
#pragma unroll
        for (int k = 0; k < NLOC_; k++) {
            float v = ls[k * 512 + f];
            pool += a2s[k] * v;
            lfv += wds[k] * v;
        }
        g_X[(size_t)b * 768 + f] = f2tf32(pool);
        g_lf[(size_t)b * 512 + f] = lfv + bd;
    }
}

extern "C" void kernel_launch(void* const* d_in, const int* in_sizes, int n_in,
                              void* d_out, int out_size) {
    const float* gf   = (const float*)d_in[0];
    const float* locl = (const float*)d_in[1];
    const float* Wq   = (const float*)d_in[2];
    const float* bq   = (const float*)d_in[3];
    const float* Wk   = (const float*)d_in[4];
    const float* Wv   = (const float*)d_in[6];
    const float* bv   = (const float*)d_in[7];
    const float* w_dr = (const float*)d_in[8];
    const float* b_dr = (const float*)d_in[9];
    const float* Wf   = (const float*)d_in[10];
    const float* bf   = (const float*)d_in[11];
    float* out = (float*)d_out;
    int B = in_sizes[0] / F_DIM;

    prep_bt1_mm<<<dim3(32, 32), dim3(16, 16)>>>(Wk, Wq);
    prep_bt1_cp<<<512, 256>>>(Wv);
    prep_bt3_mm<<<dim3(32, 32), dim3(16, 16)>>>(Wf, Wv);
    prep_bt3_cp<<<512, 256>>>(Wf);
    prep_vec<<<4, 256>>>(bq, Wk, bv, Wf, bf, w_dr);
    gemm_tf32<1><<<dim3(6, B / 128), 256>>>(gf, bv, b_dr, gf, nullptr);
    attn_pool<<<B, 256>>>(locl, w_dr, b_dr);
    gemm_tf32<3><<<dim3(4, B / 128), 256>>>(nullptr, bv, b_dr, gf, out);
}

// round 4
// speedup vs baseline: 1.5259x; 1.5259x over previous
#include <cuda_runtime.h>
#include <cuda_fp16.h>
#include <cstdint>

#define MAXB 16384

// ---------------- scratch ----------------
__device__ __align__(16) __half g_B1h[512 * 512];        // [n][k] : t = gf @ B1^T
__device__ __align__(16) __half g_B3h[512 * 1024];       // [n][k] : k<512 pooled-part, k>=512 gf-part
__device__ __align__(16) float  g_ct[512];
__device__ __align__(16) float  g_bf3[512];
__device__ __align__(16) float  g_t[(size_t)MAXB * 512];
__device__ __align__(16) __half g_X16[(size_t)MAXB * 512];   // pooled (fp16)
__device__ __align__(16) __half g_gf16[(size_t)MAXB * 512];  // gf (fp16)
__device__ __align__(16) float  g_lf[(size_t)MAXB * 512];

// ---------------- helpers ----------------
__device__ __forceinline__ uint32_t smem_u32(const void* p) {
    uint32_t a;
    asm("{ .reg .u64 t; cvta.to.shared.u64 t, %1; cvt.u32.u64 %0, t; }" : "=r"(a) : "l"(p));
    return a;
}
__device__ __forceinline__ void cp16s(uint32_t saddr, const void* src) {
    asm volatile("cp.async.cg.shared.global [%0], [%1], 16;" ::"r"(saddr), "l"(src));
}
__device__ __forceinline__ void ldm4(uint32_t r[4], uint32_t addr) {
    asm volatile("ldmatrix.sync.aligned.m8n8.x4.shared.b16 {%0,%1,%2,%3}, [%4];"
                 : "=r"(r[0]), "=r"(r[1]), "=r"(r[2]), "=r"(r[3]) : "r"(addr));
}
__device__ __forceinline__ void mma16(float c[4], const uint32_t a[4], const uint32_t b[2]) {
    asm volatile(
        "mma.sync.aligned.m16n8k16.row.col.f32.f16.f16.f32 "
        "{%0,%1,%2,%3},{%4,%5,%6,%7},{%8,%9},{%0,%1,%2,%3};"
        : "+f"(c[0]), "+f"(c[1]), "+f"(c[2]), "+f"(c[3])
        : "r"(a[0]), "r"(a[1]), "r"(a[2]), "r"(a[3]), "r"(b[0]), "r"(b[1]));
}

// ---------------- gf -> fp16 ----------------
__global__ __launch_bounds__(256) void conv16(const float4* __restrict__ src,
                                              __half2* __restrict__ dst, int n4) {
    int i = blockIdx.x * 256 + threadIdx.x;
    if (i < n4) {
        float4 v = src[i];
        dst[i * 2 + 0] = __floats2half2_rn(v.x, v.y);
        dst[i * 2 + 1] = __floats2half2_rn(v.z, v.w);
    }
}

// ---------------- fused prep (weight products, fp32 compute -> fp16 store) ----------------
__global__ __launch_bounds__(256) void prep_all(const float* __restrict__ Wq,
                                                const float* __restrict__ bq,
                                                const float* __restrict__ Wk,
                                                const float* __restrict__ Wv,
                                                const float* __restrict__ bv,
                                                const float* __restrict__ w_dr,
                                                const float* __restrict__ b_dr,
                                                const float* __restrict__ Wf,
                                                const float* __restrict__ bf) {
    int blk = blockIdx.x;
    if (blk < 3072) {
        __shared__ float sA[16][17], sB[16][17];
        int tx = threadIdx.x & 15, ty = threadIdx.x >> 4;
        int job = blk >> 10, b2 = blk & 1023;
        int c0 = (b2 & 31) * 16, r0 = (b2 >> 5) * 16;
        float acc = 0.f;
        for (int h0 = 0; h0 < 256; h0 += 16) {
            if (job == 0) {
                sA[ty][tx] = Wk[(r0 + ty) * 256 + h0 + tx];
                sB[ty][tx] = Wq[(c0 + ty) * 256 + h0 + tx];
            } else if (job == 1) {
                sA[ty][tx] = Wf[(h0 + ty) * 512 + r0 + tx];
                sB[ty][tx] = Wv[(c0 + ty) * 256 + h0 + tx];
            } else {
                sA[ty][tx] = Wf[(256 + h0 + ty) * 512 + r0 + tx];
                sB[ty][tx] = Wv[(c0 + ty) * 256 + h0 + tx];
            }
            __syncthreads();
#pragma unroll
            for (int hh = 0; hh < 16; hh++) {
                if (job == 0) acc += sA[ty][hh] * sB[tx][hh];
                else          acc += sA[hh][ty] * sB[tx][hh];
            }
            __syncthreads();
        }
        if (job == 0) {
            g_B1h[(r0 + ty) * 512 + c0 + tx] = __float2half_rn(acc);
        } else if (job == 1) {
            g_B3h[(r0 + ty) * 1024 + c0 + tx] = __float2half_rn(acc);
        } else {
            float S = 0.f;
            for (int k = 0; k < 12; k++) S += w_dr[k];
            g_B3h[(r0 + ty) * 1024 + 512 + c0 + tx] = __float2half_rn(S * acc);
        }
    } else {
        int gid = (blk - 3072) * 256 + threadIdx.x;
        if (gid < 512) {
            float a = 0.f;
            for (int h = 0; h < 256; h++) a += bq[h] * Wk[gid * 256 + h];
            g_ct[gid] = a;
        } else if (gid < 1024) {
            int n = gid - 512;
            float S = 0.f;
            for (int k = 0; k < 12; k++) S += w_dr[k];
            float bd = b_dr[0];
            float a = bf[n];
            for (int h = 0; h < 256; h++) {
                a += bv[h] * Wf[h * 512 + n];
                a += (S * bv[h] + bd) * Wf[(256 + h) * 512 + n];
            }
            g_bf3[n] = a;
        }
    }
}

// ---------------- fp16 mma.sync GEMM, 128x128xK, ldmatrix fragments ----------------
// MODE 1: g_t[B,512] = gf16 @ B1h^T + ct                       (K=512)
// MODE 3: out[B,512] = relu([X16|gf16] @ B3h^T + bf3) + lf + gf (K=1024)
#define LDH 40  // padded leading dim (halves): 80B stride => conflict-free ldmatrix

template <int MODE>
__global__ __launch_bounds__(256, 2) void gemm_h(const float* __restrict__ gf,
                                                 float* __restrict__ out) {
    constexpr int KTOT = (MODE == 1) ? 512 : 1024;
    constexpr int KT = KTOT / 32;
    __shared__ __align__(16) __half As[2][128 * LDH];
    __shared__ __align__(16) __half Bs[2][128 * LDH];
    const __half* Bt = (MODE == 1) ? g_B1h : g_B3h;

    int tid = threadIdx.x, lane = tid & 31, warp = tid >> 5;
    int wm = warp >> 2, wn = warp & 3;  // 2x4 warps -> warp tile 64(m) x 32(n)
    int m0 = blockIdx.y * 128, n0 = blockIdx.x * 128;

    float acc[4][4][4];
#pragma unroll
    for (int i = 0; i < 4; i++)
#pragma unroll
        for (int j = 0; j < 4; j++)
#pragma unroll
            for (int q = 0; q < 4; q++) acc[i][j][q] = 0.f;

    // staging: thread -> row sr (0..127), 32B half-chunk
    int sr = tid >> 1;
    int hoff = (tid & 1) * 16;                 // halves
    uint32_t dstoff = (uint32_t)(sr * LDH + hoff) * 2;  // bytes
    uint32_t aS[2] = {smem_u32(&As[0][0]), smem_u32(&As[1][0])};
    uint32_t bS[2] = {smem_u32(&Bs[0][0]), smem_u32(&Bs[1][0])};

    // fragment load offsets (halves)
    int arow = (lane & 7) + ((lane >> 3) & 1) * 8;
    int acol = ((lane >> 4) & 1) * 8;
    uint32_t aoffB = (uint32_t)((wm * 64 + arow) * LDH + acol) * 2;
    int brow = (lane & 7) + ((lane >> 4) & 1) * 8;
    int bcol = ((lane >> 3) & 1) * 8;
    uint32_t boffB = (uint32_t)((wn * 32 + brow) * LDH + bcol) * 2;

    auto stage = [&](int c, int buf) {
        const __half* ar;
        if (MODE == 1) {
            ar = g_gf16 + (size_t)(m0 + sr) * 512 + c * 32 + hoff;
        } else {
            ar = (c < 16) ? (g_X16 + (size_t)(m0 + sr) * 512 + c * 32 + hoff)
                          : (g_gf16 + (size_t)(m0 + sr) * 512 + (c - 16) * 32 + hoff);
        }
        cp16s(aS[buf] + dstoff, ar);
        cp16s(aS[buf] + dstoff + 16, ar + 8);
        const __half* br = Bt + (size_t)(n0 + sr) * KTOT + c * 32 + hoff;
        cp16s(bS[buf] + dstoff, br);
        cp16s(bS[buf] + dstoff + 16, br + 8);
        asm volatile("cp.async.commit_group;");
    };

    stage(0, 0);
    for (int kt = 0; kt < KT; kt++) {
        int cur = kt & 1;
        if (kt + 1 < KT) {
            stage(kt + 1, cur ^ 1);
            asm volatile("cp.async.wait_group 1;");
        } else {
            asm volatile("cp.async.wait_group 0;");
        }
        __syncthreads();

#pragma unroll
        for (int kk = 0; kk < 2; kk++) {
            uint32_t af[4][4];
#pragma unroll
            for (int i = 0; i < 4; i++)
                ldm4(af[i], aS[cur] + aoffB + (uint32_t)(i * 16 * LDH + kk * 16) * 2);
            uint32_t bf[2][4];
#pragma unroll
            for (int j2 = 0; j2 < 2; j2++)
                ldm4(bf[j2], bS[cur] + boffB + (uint32_t)(j2 * 16 * LDH + kk * 16) * 2);
#pragma unroll
            for (int i = 0; i < 4; i++)
#pragma unroll
                for (int j = 0; j < 4; j++)
                    mma16(acc[i][j], af[i], &bf[j >> 1][(j & 1) * 2]);
        }
        __syncthreads();
    }

    // epilogue
#pragma unroll
    for (int i = 0; i < 4; i++) {
        int row = m0 + wm * 64 + i * 16 + (lane >> 2);
#pragma unroll
        for (int j = 0; j < 4; j++) {
            int col = n0 + wn * 32 + j * 8 + (lane & 3) * 2;
#pragma unroll
            for (int h = 0; h < 2; h++) {  // h=0: row, h=1: row+8  (c2,c3)
                int rr = row + h * 8;
                float v0 = acc[i][j][h * 2 + 0];
                float v1 = acc[i][j][h * 2 + 1];
                if (MODE == 1) {
                    float2 r = make_float2(v0 + g_ct[col], v1 + g_ct[col + 1]);
                    *(float2*)&g_t[(size_t)rr * 512 + col] = r;
                } else {
                    float2 lf = *(const float2*)&g_lf[(size_t)rr * 512 + col];
                    float2 gv = *(const float2*)&gf[(size_t)rr * 512 + col];
                    float z0 = fmaxf(v0 + g_bf3[col], 0.f) + lf.x + gv.x;
                    float z1 = fmaxf(v1 + g_bf3[col + 1], 0.f) + lf.y + gv.y;
                    *(float2*)&out[(size_t)rr * 512 + col] = make_float2(z0, z1);
                }
            }
        }
    }
}

// ---------------- attention scores + pooling + lf_mean ----------------
__global__ __launch_bounds__(256) void attn_pool(const float* __restrict__ local,
                                                 const float* __restrict__ w_dr,
                                                 const float* __restrict__ b_dr) {
    __shared__ float ls[12 * 512];
    __shared__ float sred[12][8];
    __shared__ float a2s[12], wds[12];
    int b = blockIdx.x, tid = threadIdx.x;
    const float4* lb4 = (const float4*)(local + (size_t)b * 12 * 512);
    float4* ls4 = (float4*)ls;
#pragma unroll
    for (int i = 0; i < 6; i++) ls4[tid + i * 256] = lb4[tid + i * 256];
    if (tid < 12) wds[tid] = w_dr[tid];
    float tt0 = g_t[(size_t)b * 512 + tid];
    float tt1 = g_t[(size_t)b * 512 + tid + 256];
    __syncthreads();

    float p[12];
#pragma unroll
    for (int k = 0; k < 12; k++)
        p[k] = ls[k * 512 + tid] * tt0 + ls[k * 512 + tid + 256] * tt1;
#pragma unroll
    for (int k = 0; k < 12; k++)
#pragma unroll
        for (int off = 16; off; off >>= 1) p[k] += __shfl_xor_sync(0xffffffffu, p[k], off);
    if ((tid & 31) == 0) {
        int w = tid >> 5;
#pragma unroll
        for (int k = 0; k < 12; k++) sred[k][w] = p[k];
    }
    __syncthreads();
    if (tid == 0) {
        float s[12], m = -1e30f;
#pragma unroll
        for (int k = 0; k < 12; k++) {
            float v = 0.f;
#pragma unroll
            for (int w = 0; w < 8; w++) v += sred[k][w];
            v *= 0.0625f;  // 1/sqrt(256)
            s[k] = v;
            m = fmaxf(m, v);
        }
        float den = 0.f;
#pragma unroll
        for (int k = 0; k < 12; k++) { s[k] = __expf(s[k] - m); den += s[k]; }
        float inv = 1.f / den;
#pragma unroll
        for (int k = 0; k < 12; k++) a2s[k] = s[k] * inv;
    }
    __syncthreads();
    float bd = b_dr[0];
#pragma unroll
    for (int q = 0; q < 2; q++) {
        int f = tid + q * 256;
        float pool = 0.f, lfv = 0.f;
#pragma unroll
        for (int k = 0; k < 12; k++) {
            float v = ls[k * 512 + f];
            pool += a2s[k] * v;
            lfv += wds[k] * v;
        }
        g_X16[(size_t)b * 512 + f] = __float2half_rn(pool);
        g_lf[(size_t)b * 512 + f] = lfv + bd;
    }
}

extern "C" void kernel_launch(void* const* d_in, const int* in_sizes, int n_in,
                              void* d_out, int out_size) {
    const float* gf   = (const float*)d_in[0];
    const float* locl = (const float*)d_in[1];
    const float* Wq   = (const float*)d_in[2];
    const float* bq   = (const float*)d_in[3];
    const float* Wk   = (const float*)d_in[4];
    const float* Wv   = (const float*)d_in[6];
    const float* bv   = (const float*)d_in[7];
    const float* w_dr = (const float*)d_in[8];
    const float* b_dr = (const float*)d_in[9];
    const float* Wf   = (const float*)d_in[10];
    const float* bf   = (const float*)d_in[11];
    float* out = (float*)d_out;
    int B = in_sizes[0] / 512;

    __half2* gf16;
    cudaGetSymbolAddress((void**)&gf16, g_gf16);
    int n4 = B * 512 / 4;
    conv16<<<(n4 + 255) / 256, 256>>>((const float4*)gf, (__half2*)gf16, n4);
    prep_all<<<3076, 256>>>(Wq, bq, Wk, Wv, bv, w_dr, b_dr, Wf, bf);
    gemm_h<1><<<dim3(4, B / 128), 256>>>(gf, nullptr);
    attn_pool<<<B, 256>>>(locl, w_dr, b_dr);
    gemm_h<3><<<dim3(4, B / 128), 256>>>(gf, out);
}

// round 5
// speedup vs baseline: 1.6754x; 1.0980x over previous
#include <cuda_runtime.h>
#include <cuda_fp16.h>
#include <cstdint>

#define MAXB 16384

// ---------------- scratch ----------------
__device__ __align__(16) __half g_B1h[512 * 512];        // [n][k] : t = gf @ B1^T
__device__ __align__(16) __half g_B3h[512 * 1024];       // [n][k] : k<512 pooled, k>=512 gf
__device__ __align__(16) float  g_ct[512];
__device__ __align__(16) float  g_bf3[512];
__device__ __align__(16) float  g_t[(size_t)MAXB * 512];
__device__ __align__(16) __half g_X16[(size_t)MAXB * 512];   // pooled (fp16)
__device__ __align__(16) __half g_gf16[(size_t)MAXB * 512];  // gf (fp16)
__device__ __align__(16) float  g_lf[(size_t)MAXB * 512];

// ---------------- helpers ----------------
__device__ __forceinline__ uint32_t smem_u32(const void* p) {
    uint32_t a;
    asm("{ .reg .u64 t; cvta.to.shared.u64 t, %1; cvt.u32.u64 %0, t; }" : "=r"(a) : "l"(p));
    return a;
}
__device__ __forceinline__ void cp16s(uint32_t saddr, const void* src) {
    asm volatile("cp.async.cg.shared.global [%0], [%1], 16;" ::"r"(saddr), "l"(src));
}
__device__ __forceinline__ void ldm4(uint32_t r[4], uint32_t addr) {
    asm volatile("ldmatrix.sync.aligned.m8n8.x4.shared.b16 {%0,%1,%2,%3}, [%4];"
                 : "=r"(r[0]), "=r"(r[1]), "=r"(r[2]), "=r"(r[3]) : "r"(addr));
}
__device__ __forceinline__ void mma16(float c[4], const uint32_t a[4], const uint32_t b[2]) {
    asm volatile(
        "mma.sync.aligned.m16n8k16.row.col.f32.f16.f16.f32 "
        "{%0,%1,%2,%3},{%4,%5,%6,%7},{%8,%9},{%0,%1,%2,%3};"
        : "+f"(c[0]), "+f"(c[1]), "+f"(c[2]), "+f"(c[3])
        : "r"(a[0]), "r"(a[1]), "r"(a[2]), "r"(a[3]), "r"(b[0]), "r"(b[1]));
}

// ---------------- gf -> fp16 ----------------
__global__ __launch_bounds__(256) void conv16(const float4* __restrict__ src,
                                              __half2* __restrict__ dst, int n4) {
    int i = blockIdx.x * 256 + threadIdx.x;
    if (i < n4) {
        float4 v = src[i];
        dst[i * 2 + 0] = __floats2half2_rn(v.x, v.y);
        dst[i * 2 + 1] = __floats2half2_rn(v.z, v.w);
    }
}

// ---------------- fused prep ----------------
__global__ __launch_bounds__(256) void prep_all(const float* __restrict__ Wq,
                                                const float* __restrict__ bq,
                                                const float* __restrict__ Wk,
                                                const float* __restrict__ Wv,
                                                const float* __restrict__ bv,
                                                const float* __restrict__ w_dr,
                                                const float* __restrict__ b_dr,
                                                const float* __restrict__ Wf,
                                                const float* __restrict__ bf) {
    int blk = blockIdx.x;
    if (blk < 3072) {
        __shared__ float sA[16][17], sB[16][17];
        int tx = threadIdx.x & 15, ty = threadIdx.x >> 4;
        int job = blk >> 10, b2 = blk & 1023;
        int c0 = (b2 & 31) * 16, r0 = (b2 >> 5) * 16;
        float acc = 0.f;
        for (int h0 = 0; h0 < 256; h0 += 16) {
            if (job == 0) {
                sA[ty][tx] = Wk[(r0 + ty) * 256 + h0 + tx];
                sB[ty][tx] = Wq[(c0 + ty) * 256 + h0 + tx];
            } else if (job == 1) {
                sA[ty][tx] = Wf[(h0 + ty) * 512 + r0 + tx];
                sB[ty][tx] = Wv[(c0 + ty) * 256 + h0 + tx];
            } else {
                sA[ty][tx] = Wf[(256 + h0 + ty) * 512 + r0 + tx];
                sB[ty][tx] = Wv[(c0 + ty) * 256 + h0 + tx];
            }
            __syncthreads();
#pragma unroll
            for (int hh = 0; hh < 16; hh++) {
                if (job == 0) acc += sA[ty][hh] * sB[tx][hh];
                else          acc += sA[hh][ty] * sB[tx][hh];
            }
            __syncthreads();
        }
        if (job == 0) {
            g_B1h[(r0 + ty) * 512 + c0 + tx] = __float2half_rn(acc);
        } else if (job == 1) {
            g_B3h[(r0 + ty) * 1024 + c0 + tx] = __float2half_rn(acc);
        } else {
            float S = 0.f;
            for (int k = 0; k < 12; k++) S += w_dr[k];
            g_B3h[(r0 + ty) * 1024 + 512 + c0 + tx] = __float2half_rn(S * acc);
        }
    } else {
        int gid = (blk - 3072) * 256 + threadIdx.x;
        if (gid < 512) {
            float a = 0.f;
            for (int h = 0; h < 256; h++) a += bq[h] * Wk[gid * 256 + h];
            g_ct[gid] = a;
        } else if (gid < 1024) {
            int n = gid - 512;
            float S = 0.f;
            for (int k = 0; k < 12; k++) S += w_dr[k];
            float bd = b_dr[0];
            float a = bf[n];
            for (int h = 0; h < 256; h++) {
                a += bv[h] * Wf[h * 512 + n];
                a += (S * bv[h] + bd) * Wf[(256 + h) * 512 + n];
            }
            g_bf3[n] = a;
        }
    }
}

// ---------------- fp16 mma.sync GEMM, 128x128 tile, 3-stage cp.async ----------------
// MODE 1: g_t[B,512] = gf16 @ B1h^T + ct                         (K=512)
// MODE 3: out[B,512] = relu([X16|gf16] @ B3h^T + bf3) + lf + gf  (K=1024)
#define LDH 40              // padded leading dim in halves (80B row stride)
#define BUFB (128 * LDH * 2)  // bytes per operand buffer = 10240
#define SMEM_GEMM (3 * 2 * BUFB)

template <int MODE>
__global__ __launch_bounds__(256, 2) void gemm_h(const float* __restrict__ gf,
                                                 float* __restrict__ out) {
    constexpr int KTOT = (MODE == 1) ? 512 : 1024;
    constexpr int KT = KTOT / 32;
    extern __shared__ __align__(16) char dsm[];
    const __half* Bt = (MODE == 1) ? g_B1h : g_B3h;

    int tid = threadIdx.x, lane = tid & 31, warp = tid >> 5;
    int wm = warp >> 2, wn = warp & 3;  // 2x4 warps -> warp tile 64(m) x 32(n)
    int m0 = blockIdx.y * 128, n0 = blockIdx.x * 128;

    uint32_t sb = smem_u32(dsm);
    uint32_t Ab[3], Bb[3];
#pragma unroll
    for (int s = 0; s < 3; s++) { Ab[s] = sb + s * BUFB; Bb[s] = sb + 3 * BUFB + s * BUFB; }

    float acc[4][4][4];
#pragma unroll
    for (int i = 0; i < 4; i++)
#pragma unroll
        for (int j = 0; j < 4; j++)
#pragma unroll
            for (int q = 0; q < 4; q++) acc[i][j][q] = 0.f;

    int sr = tid >> 1;
    int hoff = (tid & 1) * 16;
    uint32_t dstoff = (uint32_t)(sr * LDH + hoff) * 2;

    int arow = (lane & 7) + ((lane >> 3) & 1) * 8;
    int acol = ((lane >> 4) & 1) * 8;
    uint32_t aoffB = (uint32_t)((wm * 64 + arow) * LDH + acol) * 2;
    int brow = (lane & 7) + ((lane >> 4) & 1) * 8;
    int bcol = ((lane >> 3) & 1) * 8;
    uint32_t boffB = (uint32_t)((wn * 32 + brow) * LDH + bcol) * 2;

    auto stage = [&](int c, int buf) {
        const __half* ar;
        if (MODE == 1) {
            ar = g_gf16 + (size_t)(m0 + sr) * 512 + c * 32 + hoff;
        } else {
            ar = (c < 16) ? (g_X16 + (size_t)(m0 + sr) * 512 + c * 32 + hoff)
                          : (g_gf16 + (size_t)(m0 + sr) * 512 + (c - 16) * 32 + hoff);
        }
        cp16s(Ab[buf] + dstoff, ar);
        cp16s(Ab[buf] + dstoff + 16, ar + 8);
        const __half* br = Bt + (size_t)(n0 + sr) * KTOT + c * 32 + hoff;
        cp16s(Bb[buf] + dstoff, br);
        cp16s(Bb[buf] + dstoff + 16, br + 8);
        asm volatile("cp.async.commit_group;");
    };

    stage(0, 0);
    stage(1, 1);
    for (int kt = 0; kt < KT; kt++) {
        if (kt < KT - 1) asm volatile("cp.async.wait_group 1;");
        else             asm volatile("cp.async.wait_group 0;");
        __syncthreads();
        if (kt + 2 < KT) stage(kt + 2, (kt + 2) % 3);

        int cur = kt % 3;
#pragma unroll
        for (int kk = 0; kk < 2; kk++) {
            uint32_t af[4][4];
#pragma unroll
            for (int i = 0; i < 4; i++)
                ldm4(af[i], Ab[cur] + aoffB + (uint32_t)(i * 16 * LDH + kk * 16) * 2);
            uint32_t bfg[2][4];
#pragma unroll
            for (int j2 = 0; j2 < 2; j2++)
                ldm4(bfg[j2], Bb[cur] + boffB + (uint32_t)(j2 * 16 * LDH + kk * 16) * 2);
#pragma unroll
            for (int i = 0; i < 4; i++)
#pragma unroll
                for (int j = 0; j < 4; j++)
                    mma16(acc[i][j], af[i], &bfg[j >> 1][(j & 1) * 2]);
        }
    }

#pragma unroll
    for (int i = 0; i < 4; i++) {
        int row = m0 + wm * 64 + i * 16 + (lane >> 2);
#pragma unroll
        for (int j = 0; j < 4; j++) {
            int col = n0 + wn * 32 + j * 8 + (lane & 3) * 2;
#pragma unroll
            for (int h = 0; h < 2; h++) {
                int rr = row + h * 8;
                float v0 = acc[i][j][h * 2 + 0];
                float v1 = acc[i][j][h * 2 + 1];
                if (MODE == 1) {
                    *(float2*)&g_t[(size_t)rr * 512 + col] =
                        make_float2(v0 + g_ct[col], v1 + g_ct[col + 1]);
                } else {
                    float2 lf = *(const float2*)&g_lf[(size_t)rr * 512 + col];
                    float2 gv = *(const float2*)&gf[(size_t)rr * 512 + col];
                    float z0 = fmaxf(v0 + g_bf3[col], 0.f) + lf.x + gv.x;
                    float z1 = fmaxf(v1 + g_bf3[col + 1], 0.f) + lf.y + gv.y;
                    *(float2*)&out[(size_t)rr * 512 + col] = make_float2(z0, z1);
                }
            }
        }
    }
}

// ---------------- attention + pooling + lf_mean (register-resident, local read once) ----------------
__global__ __launch_bounds__(256) void attn_pool(const float* __restrict__ local,
                                                 const float* __restrict__ w_dr,
                                                 const float* __restrict__ b_dr) {
    __shared__ float sred[12][8];
    __shared__ float a2s[12], wds[12];
    int b = blockIdx.x, tid = threadIdx.x;
    const float2* lb2 = (const float2*)(local + (size_t)b * 12 * 512);

    if (tid < 12) wds[tid] = w_dr[tid];
    float2 tt = ((const float2*)(g_t + (size_t)b * 512))[tid];

    float2 lv[12];
#pragma unroll
    for (int k = 0; k < 12; k++) lv[k] = lb2[k * 256 + tid];

    float p[12];
#pragma unroll
    for (int k = 0; k < 12; k++) p[k] = lv[k].x * tt.x + lv[k].y * tt.y;
#pragma unroll
    for (int k = 0; k < 12; k++)
#pragma unroll
        for (int off = 16; off; off >>= 1) p[k] += __shfl_xor_sync(0xffffffffu, p[k], off);
    if ((tid & 31) == 0) {
        int w = tid >> 5;
#pragma unroll
        for (int k = 0; k < 12; k++) sred[k][w] = p[k];
    }
    __syncthreads();
    if (tid == 0) {
        float s[12], m = -1e30f;
#pragma unroll
        for (int k = 0; k < 12; k++) {
            float v = 0.f;
#pragma unroll
            for (int w = 0; w < 8; w++) v += sred[k][w];
            v *= 0.0625f;  // 1/sqrt(256)
            s[k] = v;
            m = fmaxf(m, v);
        }
        float den = 0.f;
#pragma unroll
        for (int k = 0; k < 12; k++) { s[k] = __expf(s[k] - m); den += s[k]; }
        float inv = 1.f / den;
#pragma unroll
        for (int k = 0; k < 12; k++) a2s[k] = s[k] * inv;
    }
    __syncthreads();

    float bd = b_dr[0];
    float px = 0.f, py = 0.f, lx = 0.f, ly = 0.f;
#pragma unroll
    for (int k = 0; k < 12; k++) {
        float a = a2s[k], w = wds[k];
        px += a * lv[k].x;  py += a * lv[k].y;
        lx += w * lv[k].x;  ly += w * lv[k].y;
    }
    ((__half2*)g_X16)[(size_t)b * 256 + tid] = __floats2half2_rn(px, py);
    ((float2*)g_lf)[(size_t)b * 256 + tid] = make_float2(lx + bd, ly + bd);
}

extern "C" void kernel_launch(void* const* d_in, const int* in_sizes, int n_in,
                              void* d_out, int out_size) {
    const float* gf   = (const float*)d_in[0];
    const float* locl = (const float*)d_in[1];
    const float* Wq   = (const float*)d_in[2];
    const float* bq   = (const float*)d_in[3];
    const float* Wk   = (const float*)d_in[4];
    const float* Wv   = (const float*)d_in[6];
    const float* bv   = (const float*)d_in[7];
    const float* w_dr = (const float*)d_in[8];
    const float* b_dr = (const float*)d_in[9];
    const float* Wf   = (const float*)d_in[10];
    const float* bf   = (const float*)d_in[11];
    float* out = (float*)d_out;
    int B = in_sizes[0] / 512;

    cudaFuncSetAttribute(gemm_h<1>, cudaFuncAttributeMaxDynamicSharedMemorySize, SMEM_GEMM);
    cudaFuncSetAttribute(gemm_h<3>, cudaFuncAttributeMaxDynamicSharedMemorySize, SMEM_GEMM);

    __half2* gf16;
    cudaGetSymbolAddress((void**)&gf16, g_gf16);
    int n4 = B * 512 / 4;
    conv16<<<(n4 + 255) / 256, 256>>>((const float4*)gf, (__half2*)gf16, n4);
    prep_all<<<3076, 256>>>(Wq, bq, Wk, Wv, bv, w_dr, b_dr, Wf, bf);
    gemm_h<1><<<dim3(4, B / 128), 256, SMEM_GEMM>>>(gf, nullptr);
    attn_pool<<<B, 256>>>(locl, w_dr, b_dr);
    gemm_h<3><<<dim3(4, B / 128), 256, SMEM_GEMM>>>(gf, out);
}